// round 8
// baseline (speedup 1.0000x reference)
#include <cuda_runtime.h>
#include <cuda_bf16.h>
#include <cstdint>

#define HWSZ 65536
#define FEAT (16*64*HWSZ)
#define PLANE ((size_t)16*HWSZ*64)

__device__ float g_featA[FEAT];
__device__ float g_featB[FEAT];
__device__ unsigned char g_wblk[147456];   // [tap 9][co 64][K 128] bf16, swizzled

#define SA_OFF 147456
#define SLOT_SZ 19008                      // 2 planes x 66px x 144B (padded stride)
#define SMEM_BLK (147456 + 4 * SLOT_SZ)    // 223,488 B

__device__ __forceinline__ float prelu_f(float v, float a) { return v >= 0.f ? v : a * v; }

__device__ __forceinline__ uint32_t smem_u32(const void* p) {
    uint32_t a;
    asm("{ .reg .u64 t; cvta.to.shared.u64 t, %1; cvt.u32.u64 %0, t; }" : "=r"(a) : "l"(p));
    return a;
}
__device__ __forceinline__ void ldsm4(uint32_t* r, uint32_t addr) {
    asm volatile("ldmatrix.sync.aligned.m8n8.x4.shared.b16 {%0,%1,%2,%3}, [%4];"
                 : "=r"(r[0]), "=r"(r[1]), "=r"(r[2]), "=r"(r[3]) : "r"(addr));
}
__device__ __forceinline__ void mma16816(float* d, const uint32_t* a, uint32_t b0, uint32_t b1) {
    asm volatile("mma.sync.aligned.m16n8k16.row.col.f32.bf16.bf16.f32 "
                 "{%0,%1,%2,%3},{%4,%5,%6,%7},{%8,%9},{%0,%1,%2,%3};"
                 : "+f"(d[0]), "+f"(d[1]), "+f"(d[2]), "+f"(d[3])
                 : "r"(a[0]), "r"(a[1]), "r"(a[2]), "r"(a[3]), "r"(b0), "r"(b1));
}
__device__ __forceinline__ void cpa16(uint32_t dst, const void* src, int sz) {
    asm volatile("cp.async.cg.shared.global [%0], [%1], 16, %2;" :: "r"(dst), "l"(src), "r"(sz));
}
__device__ __forceinline__ void cpa16f(uint32_t dst, const void* src) {
    asm volatile("cp.async.cg.shared.global [%0], [%1], 16;" :: "r"(dst), "l"(src));
}
#define CPA_COMMIT() asm volatile("cp.async.commit_group;")
#define CPA_WAIT0()  asm volatile("cp.async.wait_group 0;")

// ---- weight prep: Wb fp32 -> swizzled [tap][co][K=128: wh(64)|wl(64)] ----
__global__ void wprep_kernel(const float* __restrict__ Wb, unsigned char* __restrict__ wsp) {
    int i = blockIdx.x * 256 + threadIdx.x;
    if (i >= 9 * 64 * 128) return;
    int k = i & 127, co = (i >> 7) & 63, tap = i >> 13;
    int ci = k & 63, seg = k >> 6;
    float w = Wb[co * 576 + ci * 9 + tap];
    __nv_bfloat16 h = __float2bfloat16(w);
    __nv_bfloat16 v = seg ? __float2bfloat16(w - __bfloat162float(h)) : h;
    int kb = 2 * k;
    int off = (kb & 128) | ((kb & 127) ^ ((co & 7) << 4));
    *(__nv_bfloat16*)(wsp + tap * 16384 + co * 256 + off) = v;
}

// ---------------- CS sampling conv (fp32) ----------------------------------
__global__ void cs_kernel(const float* __restrict__ x, const float* __restrict__ Wcs,
                          float* __restrict__ csy) {
    const int pg = blockIdx.x, n = blockIdx.y, f = threadIdx.x;
    __shared__ float sX[8][32];
    __shared__ float sW[256][33];
    float acc[8] = {};
    for (int k0 = 0; k0 < 1024; k0 += 32) {
        const int i = k0 >> 5;
        int p = threadIdx.x >> 5, kk = threadIdx.x & 31;
        sX[p][kk] = x[n * HWSZ + (pg * 32 + i) * 256 + p * 32 + kk];
        for (int e = threadIdx.x; e < 8192; e += 256)
            sW[e >> 5][e & 31] = Wcs[(e >> 5) * 1024 + k0 + (e & 31)];
        __syncthreads();
#pragma unroll
        for (int q = 0; q < 32; q++) {
            float w = sW[f][q];
#pragma unroll
            for (int pp = 0; pp < 8; pp++) acc[pp] += sX[pp][q] * w;
        }
        __syncthreads();
    }
#pragma unroll
    for (int pp = 0; pp < 8; pp++) csy[(n * 256 + f) * 64 + pg * 8 + pp] = acc[pp];
}

// ---------------- init reconstruction (fp32) -------------------------------
__global__ void init_kernel(const float* __restrict__ csy, const float* __restrict__ Wi,
                            float* __restrict__ initrec) {
    const int cb = blockIdx.x * 128, n = blockIdx.y;
    const int cg = threadIdx.x >> 3, pgl = threadIdx.x & 7;
    __shared__ float sX[32][64];
    __shared__ float sW[128][33];
    float acc[4][8] = {};
    for (int k0 = 0; k0 < 256; k0 += 32) {
        for (int e = threadIdx.x; e < 2048; e += 256)
            sX[e >> 6][e & 63] = csy[(n * 256 + k0 + (e >> 6)) * 64 + (e & 63)];
        for (int e = threadIdx.x; e < 4096; e += 256)
            sW[e >> 5][e & 31] = Wi[(cb + (e >> 5)) * 256 + k0 + (e & 31)];
        __syncthreads();
#pragma unroll
        for (int kk = 0; kk < 32; kk++) {
            float w0 = sW[cg*4+0][kk], w1 = sW[cg*4+1][kk], w2 = sW[cg*4+2][kk], w3 = sW[cg*4+3][kk];
#pragma unroll
            for (int pp = 0; pp < 8; pp++) {
                float xv = sX[kk][pgl * 8 + pp];
                acc[0][pp] += w0*xv; acc[1][pp] += w1*xv; acc[2][pp] += w2*xv; acc[3][pp] += w3*xv;
            }
        }
        __syncthreads();
    }
#pragma unroll
    for (int jc = 0; jc < 4; jc++) {
        int c = cb + cg * 4 + jc, jj = c >> 5, ii = c & 31;
#pragma unroll
        for (int pp = 0; pp < 8; pp++) {
            int pos = pgl * 8 + pp, by = pos >> 3, bx = pos & 7;
            initrec[n * HWSZ + (by * 32 + ii) * 256 + (bx * 32 + jj)] = acc[jc][pp];
        }
    }
}

// ------- first conv 1->64 + PReLU -> hi/lo bf16 planes ---------------------
__global__ void first_kernel(const float* __restrict__ initrec, const float* __restrict__ Wf,
                             const float* __restrict__ aM,
                             __nv_bfloat16* __restrict__ outH, __nv_bfloat16* __restrict__ outL) {
    const int tx = blockIdx.x, ty = blockIdx.y, n = blockIdx.z;
    __shared__ float sI[18][18];
    __shared__ float sWf[576];
    for (int e = threadIdx.x; e < 324; e += 256) {
        int yy = e / 18, xx = e % 18, gy = ty * 16 - 1 + yy, gx = tx * 16 - 1 + xx;
        sI[yy][xx] = ((unsigned)gy < 256u && (unsigned)gx < 256u) ? initrec[n * HWSZ + gy * 256 + gx] : 0.f;
    }
    for (int e = threadIdx.x; e < 576; e += 256) sWf[e] = Wf[e];
    __syncthreads();
    const float a = aM[0];
    const int co = threadIdx.x & 63, pl = threadIdx.x >> 6;
    float wr[9];
#pragma unroll
    for (int k = 0; k < 9; k++) wr[k] = sWf[co * 9 + k];
    for (int pxi = 0; pxi < 64; pxi++) {
        int px = pxi * 4 + pl, r = px >> 4, c = px & 15;
        float s = 0.f;
#pragma unroll
        for (int ky = 0; ky < 3; ky++)
#pragma unroll
            for (int kx = 0; kx < 3; kx++) s += wr[ky * 3 + kx] * sI[r + ky][c + kx];
        s = prelu_f(s, a);
        __nv_bfloat16 h = __float2bfloat16(s);
        __nv_bfloat16 l = __float2bfloat16(s - __bfloat162float(h));
        size_t ad = ((size_t)(n * HWSZ + (ty * 16 + r) * 256 + tx * 16 + c)) * 64 + co;
        outH[ad] = h;
        outL[ad] = l;
    }
}

// ---------- res-block conv 64->64: 2-row tiles, B resident -----------------
// grid (64, 16): x-col = (bx&3)*64, y-group = (bx>>2)*16. 256 thr, 8 warps.
// Slab slot: [plane 2][px 66][144B] padded stride (conflict-free, no swizzle).
__device__ __forceinline__ void load_row(uint32_t sb, const __nv_bfloat16* inH,
                                         const __nv_bfloat16* inL, int n, int y,
                                         int x0, int rel, int tid) {
    uint32_t base = sb + SA_OFF + (uint32_t)(rel & 3) * SLOT_SZ;
    for (int idx = tid; idx < 1056; idx += 256) {
        int plane = idx >= 528;
        int i2 = plane ? idx - 528 : idx;
        int px = i2 >> 3, ch = i2 & 7;
        int gx = x0 - 1 + px;
        bool ok = (unsigned)y < 256u && (unsigned)gx < 256u;
        const __nv_bfloat16* bp = plane ? inL : inH;
        const __nv_bfloat16* sp = ok ? bp + ((size_t)(n * HWSZ + y * 256 + gx)) * 64 + ch * 8 : bp;
        cpa16(base + (uint32_t)plane * 9504 + px * 144 + ch * 16, sp, ok ? 16 : 0);
    }
}

template <bool RES>
__global__ void __launch_bounds__(256, 1) blk_mma(
    const __nv_bfloat16* __restrict__ inH, const __nv_bfloat16* __restrict__ inL,
    const unsigned char* __restrict__ wblk, const float* __restrict__ aB,
    __nv_bfloat16* __restrict__ outH, __nv_bfloat16* __restrict__ outL) {
    extern __shared__ unsigned char sm[];
    const uint32_t sb = smem_u32(sm);
    const int tid = threadIdx.x, w = tid >> 5, lane = tid & 31;
    const int n = blockIdx.y, x0 = (blockIdx.x & 3) * 64, y0 = (blockIdx.x >> 2) * 16;

    // B: all 9 taps once
    {
        const uint4* s = (const uint4*)wblk;
        for (int i = tid; i < 9216; i += 256) cpa16f(sb + i * 16, s + i);
    }
    load_row(sb, inH, inL, n, y0 - 1, x0, 0, tid);
    load_row(sb, inH, inL, n, y0,     x0, 1, tid);
    CPA_COMMIT();

    // per-lane constants
    const int mf = w & 3, co0 = (w >> 2) * 32;
    const uint32_t pxoff = (uint32_t)((mf * 16 + (lane & 15)) * 144) + (((lane >> 4) & 1) << 4);
    const int co_l = (lane & 7) + ((lane >> 4) & 1) * 8;
    const int kb_l = ((lane >> 3) & 1) * 16;
    const int sx = (lane & 7) << 4;
    uint32_t offk[8];
#pragma unroll
    for (int j = 0; j < 8; j++) {
        int kb = j * 32 + kb_l;
        offk[j] = (uint32_t)((kb & 128) | ((kb & 127) ^ sx));
    }
    const uint32_t bbase = sb + (uint32_t)(co0 + co_l) * 256;
    const float a = aB[0];

    for (int t = 0; t < 8; t++) {
        load_row(sb, inH, inL, n, y0 + 2 * t + 1, x0, 2 * t + 2, tid);
        load_row(sb, inH, inL, n, y0 + 2 * t + 2, x0, 2 * t + 3, tid);
        CPA_COMMIT();
        CPA_WAIT0();
        __syncthreads();

        float acc[2][4][4];
#pragma unroll
        for (int r = 0; r < 2; r++)
#pragma unroll
            for (int i = 0; i < 4; i++)
#pragma unroll
                for (int j = 0; j < 4; j++) acc[r][i][j] = 0.f;

#pragma unroll
        for (int ky = 0; ky < 3; ky++) {
#pragma unroll
            for (int kx = 0; kx < 3; kx++) {
                uint32_t ah[2][4][4], al[2][4][4];
#pragma unroll
                for (int r = 0; r < 2; r++) {
                    const uint32_t aH = sb + SA_OFF +
                        (uint32_t)((2 * t + r + ky) & 3) * SLOT_SZ + pxoff + kx * 144;
#pragma unroll
                    for (int q = 0; q < 4; q++) {
                        ldsm4(ah[r][q], aH + q * 32);
                        ldsm4(al[r][q], aH + 9504 + q * 32);
                    }
                }
                const uint32_t bt = bbase + (uint32_t)(ky * 3 + kx) * 16384;
#pragma unroll
                for (int np = 0; np < 2; np++) {
                    const uint32_t bb = bt + np * 4096;
#pragma unroll
                    for (int ks = 0; ks < 4; ks++) {   // wh: x-hi and x-lo terms
                        uint32_t b[4];
                        ldsm4(b, bb + offk[ks]);
#pragma unroll
                        for (int r = 0; r < 2; r++) {
                            mma16816(acc[r][np*2+0], ah[r][ks], b[0], b[1]);
                            mma16816(acc[r][np*2+1], ah[r][ks], b[2], b[3]);
                            mma16816(acc[r][np*2+0], al[r][ks], b[0], b[1]);
                            mma16816(acc[r][np*2+1], al[r][ks], b[2], b[3]);
                        }
                    }
#pragma unroll
                    for (int ks = 0; ks < 4; ks++) {   // wl: x-hi only
                        uint32_t b[4];
                        ldsm4(b, bb + offk[4 + ks]);
#pragma unroll
                        for (int r = 0; r < 2; r++) {
                            mma16816(acc[r][np*2+0], ah[r][ks], b[0], b[1]);
                            mma16816(acc[r][np*2+1], ah[r][ks], b[2], b[3]);
                        }
                    }
                }
            }
        }

        // epilogue: residual + PReLU + split store (2 rows)
        const int r0 = lane >> 2;
#pragma unroll
        for (int r = 0; r < 2; r++) {
            const size_t rowbase = (size_t)(n * HWSZ + (y0 + 2 * t + r) * 256 + x0 + mf * 16);
#pragma unroll
            for (int h = 0; h < 2; h++) {
                size_t pa = (rowbase + r0 + h * 8) * 64 + co0 + (lane & 3) * 2;
#pragma unroll
                for (int nf = 0; nf < 4; nf++) {
                    size_t ad = pa + nf * 8;
                    float v0 = acc[r][nf][h * 2 + 0], v1 = acc[r][nf][h * 2 + 1];
                    if (RES) {
                        uint32_t h2 = *(const uint32_t*)(outH + ad);
                        uint32_t l2 = *(const uint32_t*)(outL + ad);
                        v0 += __bfloat162float(__ushort_as_bfloat16((unsigned short)(h2 & 0xffff))) +
                              __bfloat162float(__ushort_as_bfloat16((unsigned short)(l2 & 0xffff)));
                        v1 += __bfloat162float(__ushort_as_bfloat16((unsigned short)(h2 >> 16))) +
                              __bfloat162float(__ushort_as_bfloat16((unsigned short)(l2 >> 16)));
                    }
                    v0 = prelu_f(v0, a);
                    v1 = prelu_f(v1, a);
                    __nv_bfloat16 h0 = __float2bfloat16(v0), h1 = __float2bfloat16(v1);
                    __nv_bfloat16 l0 = __float2bfloat16(v0 - __bfloat162float(h0));
                    __nv_bfloat16 l1 = __float2bfloat16(v1 - __bfloat162float(h1));
                    *(uint32_t*)(outH + ad) = (uint32_t)__bfloat16_as_ushort(h0) |
                                              ((uint32_t)__bfloat16_as_ushort(h1) << 16);
                    *(uint32_t*)(outL + ad) = (uint32_t)__bfloat16_as_ushort(l0) |
                                              ((uint32_t)__bfloat16_as_ushort(l1) << 16);
                }
            }
        }
        __syncthreads();   // protect slab slots before next iter's loads
    }
}

// --------- last conv: (feat planes + initrec) -> 1 channel -----------------
__global__ void last_kernel(const __nv_bfloat16* __restrict__ featH,
                            const __nv_bfloat16* __restrict__ featL,
                            const float* __restrict__ initrec,
                            const float* __restrict__ Wl, float* __restrict__ out) {
    const int tx = blockIdx.x, ty = blockIdx.y, n = blockIdx.z;
    __shared__ float sInit[18][18];
    __shared__ float sIn[8][18][20];
    __shared__ float sWl[576];
    for (int e = threadIdx.x; e < 324; e += 256) {
        int yy = e / 18, xx = e % 18, gy = ty * 16 - 1 + yy, gx = tx * 16 - 1 + xx;
        sInit[yy][xx] = ((unsigned)gy < 256u && (unsigned)gx < 256u) ? initrec[n * HWSZ + gy * 256 + gx] : 0.f;
    }
    for (int e = threadIdx.x; e < 576; e += 256) sWl[e] = Wl[e];
    __syncthreads();
    const int r = threadIdx.x >> 4, c = threadIdx.x & 15;
    float acc = 0.f;
    for (int ci0 = 0; ci0 < 64; ci0 += 8) {
        for (int e = threadIdx.x; e < 2592; e += 256) {
            int px = e >> 3, ci = e & 7, yy = px / 18, xx = px % 18;
            int gy = ty * 16 - 1 + yy, gx = tx * 16 - 1 + xx;
            float v = 0.f;
            if ((unsigned)gy < 256u && (unsigned)gx < 256u) {
                size_t ad = (size_t)(n * HWSZ + gy * 256 + gx) * 64 + ci0 + ci;
                v = __bfloat162float(featH[ad]) + __bfloat162float(featL[ad]);
            }
            sIn[ci][yy][xx] = v + sInit[yy][xx];
        }
        __syncthreads();
#pragma unroll 1
        for (int ci = 0; ci < 8; ci++)
#pragma unroll
            for (int ky = 0; ky < 3; ky++)
#pragma unroll
                for (int kx = 0; kx < 3; kx++)
                    acc += sIn[ci][r + ky][c + kx] * sWl[(ci0 + ci) * 9 + ky * 3 + kx];
        __syncthreads();
    }
    out[n * HWSZ + (ty * 16 + r) * 256 + (tx * 16 + c)] = acc;
}

// ---------------------------------------------------------------------------
extern "C" void kernel_launch(void* const* d_in, const int* in_sizes, int n_in,
                              void* d_out, int out_size) {
    (void)in_sizes; (void)n_in; (void)out_size;
    const float* x   = (const float*)d_in[0];
    const float* Wcs = (const float*)d_in[1];
    const float* Wi  = (const float*)d_in[2];
    const float* Wf  = (const float*)d_in[3];
    const float* Wb  = (const float*)d_in[4];
    const float* Wl  = (const float*)d_in[5];
    const float* aM  = (const float*)d_in[6];
    const float* aB  = (const float*)d_in[7];

    float* out     = (float*)d_out;
    float* csy     = out + 16 * HWSZ;
    float* initrec = csy + 16 * 256 * 64;

    void *pA = nullptr, *pB = nullptr, *pW = nullptr;
    cudaGetSymbolAddress(&pA, g_featA);
    cudaGetSymbolAddress(&pB, g_featB);
    cudaGetSymbolAddress(&pW, g_wblk);
    __nv_bfloat16* hiA = (__nv_bfloat16*)pA;
    __nv_bfloat16* loA = hiA + PLANE;
    __nv_bfloat16* hiB = (__nv_bfloat16*)pB;
    __nv_bfloat16* loB = hiB + PLANE;
    unsigned char* wblk = (unsigned char*)pW;

    cudaFuncSetAttribute(blk_mma<false>, cudaFuncAttributeMaxDynamicSharedMemorySize, SMEM_BLK);
    cudaFuncSetAttribute(blk_mma<true>,  cudaFuncAttributeMaxDynamicSharedMemorySize, SMEM_BLK);

    wprep_kernel<<<(9 * 64 * 128 + 255) / 256, 256>>>(Wb, wblk);
    cs_kernel<<<dim3(8, 16), 256>>>(x, Wcs, csy);
    init_kernel<<<dim3(8, 16), 256>>>(csy, Wi, initrec);
    first_kernel<<<dim3(16, 16, 16), 256>>>(initrec, Wf, aM, hiA, loA);

    for (int i = 0; i < 4; i++) {
        blk_mma<false><<<dim3(64, 16), 256, SMEM_BLK>>>(hiA, loA, wblk, aB, hiB, loB);
        blk_mma<true><<<dim3(64, 16), 256, SMEM_BLK>>>(hiB, loB, wblk, aB, hiA, loA);
    }
    last_kernel<<<dim3(16, 16, 16), 256>>>(hiA, loA, initrec, Wl, out);
}

// round 9
// speedup vs baseline: 1.0472x; 1.0472x over previous
#include <cuda_runtime.h>
#include <cuda_bf16.h>
#include <cstdint>

#define HWSZ 65536
#define FEAT (16*64*HWSZ)
#define PLANE ((size_t)16*HWSZ*64)

__device__ float g_featA[FEAT];
__device__ float g_featB[FEAT];
__device__ unsigned char g_wblk[147456];   // [tap 9][co 64][K 128] bf16, swizzled

#define SA_OFF 147456
#define SLOT_SZ 16896                      // 2 planes x 66px x 128B, XOR-swizzled
#define SMEM_BLK (147456 + 5 * SLOT_SZ)    // 231,936 B

__device__ __forceinline__ float prelu_f(float v, float a) { return v >= 0.f ? v : a * v; }

__device__ __forceinline__ uint32_t smem_u32(const void* p) {
    uint32_t a;
    asm("{ .reg .u64 t; cvta.to.shared.u64 t, %1; cvt.u32.u64 %0, t; }" : "=r"(a) : "l"(p));
    return a;
}
__device__ __forceinline__ void ldsm4(uint32_t* r, uint32_t addr) {
    asm volatile("ldmatrix.sync.aligned.m8n8.x4.shared.b16 {%0,%1,%2,%3}, [%4];"
                 : "=r"(r[0]), "=r"(r[1]), "=r"(r[2]), "=r"(r[3]) : "r"(addr));
}
__device__ __forceinline__ void mma16816(float* d, const uint32_t* a, uint32_t b0, uint32_t b1) {
    asm volatile("mma.sync.aligned.m16n8k16.row.col.f32.bf16.bf16.f32 "
                 "{%0,%1,%2,%3},{%4,%5,%6,%7},{%8,%9},{%0,%1,%2,%3};"
                 : "+f"(d[0]), "+f"(d[1]), "+f"(d[2]), "+f"(d[3])
                 : "r"(a[0]), "r"(a[1]), "r"(a[2]), "r"(a[3]), "r"(b0), "r"(b1));
}
__device__ __forceinline__ void cpa16(uint32_t dst, const void* src, int sz) {
    asm volatile("cp.async.cg.shared.global [%0], [%1], 16, %2;" :: "r"(dst), "l"(src), "r"(sz));
}
__device__ __forceinline__ void cpa16f(uint32_t dst, const void* src) {
    asm volatile("cp.async.cg.shared.global [%0], [%1], 16;" :: "r"(dst), "l"(src));
}
#define CPA_COMMIT() asm volatile("cp.async.commit_group;")
#define CPA_WAIT1()  asm volatile("cp.async.wait_group 1;")

// ---- weight prep: Wb fp32 -> swizzled [tap][co][K=128: wh(64)|wl(64)] ----
__global__ void wprep_kernel(const float* __restrict__ Wb, unsigned char* __restrict__ wsp) {
    int i = blockIdx.x * 256 + threadIdx.x;
    if (i >= 9 * 64 * 128) return;
    int k = i & 127, co = (i >> 7) & 63, tap = i >> 13;
    int ci = k & 63, seg = k >> 6;
    float w = Wb[co * 576 + ci * 9 + tap];
    __nv_bfloat16 h = __float2bfloat16(w);
    __nv_bfloat16 v = seg ? __float2bfloat16(w - __bfloat162float(h)) : h;
    int kb = 2 * k;
    int off = (kb & 128) | ((kb & 127) ^ ((co & 7) << 4));
    *(__nv_bfloat16*)(wsp + tap * 16384 + co * 256 + off) = v;
}

// ---------------- CS sampling conv (fp32) ----------------------------------
__global__ void cs_kernel(const float* __restrict__ x, const float* __restrict__ Wcs,
                          float* __restrict__ csy) {
    const int pg = blockIdx.x, n = blockIdx.y, f = threadIdx.x;
    __shared__ float sX[8][32];
    __shared__ float sW[256][33];
    float acc[8] = {};
    for (int k0 = 0; k0 < 1024; k0 += 32) {
        const int i = k0 >> 5;
        int p = threadIdx.x >> 5, kk = threadIdx.x & 31;
        sX[p][kk] = x[n * HWSZ + (pg * 32 + i) * 256 + p * 32 + kk];
        for (int e = threadIdx.x; e < 8192; e += 256)
            sW[e >> 5][e & 31] = Wcs[(e >> 5) * 1024 + k0 + (e & 31)];
        __syncthreads();
#pragma unroll
        for (int q = 0; q < 32; q++) {
            float w = sW[f][q];
#pragma unroll
            for (int pp = 0; pp < 8; pp++) acc[pp] += sX[pp][q] * w;
        }
        __syncthreads();
    }
#pragma unroll
    for (int pp = 0; pp < 8; pp++) csy[(n * 256 + f) * 64 + pg * 8 + pp] = acc[pp];
}

// ---------------- init reconstruction (fp32) -------------------------------
__global__ void init_kernel(const float* __restrict__ csy, const float* __restrict__ Wi,
                            float* __restrict__ initrec) {
    const int cb = blockIdx.x * 128, n = blockIdx.y;
    const int cg = threadIdx.x >> 3, pgl = threadIdx.x & 7;
    __shared__ float sX[32][64];
    __shared__ float sW[128][33];
    float acc[4][8] = {};
    for (int k0 = 0; k0 < 256; k0 += 32) {
        for (int e = threadIdx.x; e < 2048; e += 256)
            sX[e >> 6][e & 63] = csy[(n * 256 + k0 + (e >> 6)) * 64 + (e & 63)];
        for (int e = threadIdx.x; e < 4096; e += 256)
            sW[e >> 5][e & 31] = Wi[(cb + (e >> 5)) * 256 + k0 + (e & 31)];
        __syncthreads();
#pragma unroll
        for (int kk = 0; kk < 32; kk++) {
            float w0 = sW[cg*4+0][kk], w1 = sW[cg*4+1][kk], w2 = sW[cg*4+2][kk], w3 = sW[cg*4+3][kk];
#pragma unroll
            for (int pp = 0; pp < 8; pp++) {
                float xv = sX[kk][pgl * 8 + pp];
                acc[0][pp] += w0*xv; acc[1][pp] += w1*xv; acc[2][pp] += w2*xv; acc[3][pp] += w3*xv;
            }
        }
        __syncthreads();
    }
#pragma unroll
    for (int jc = 0; jc < 4; jc++) {
        int c = cb + cg * 4 + jc, jj = c >> 5, ii = c & 31;
#pragma unroll
        for (int pp = 0; pp < 8; pp++) {
            int pos = pgl * 8 + pp, by = pos >> 3, bx = pos & 7;
            initrec[n * HWSZ + (by * 32 + ii) * 256 + (bx * 32 + jj)] = acc[jc][pp];
        }
    }
}

// ------- first conv 1->64 + PReLU -> hi/lo bf16 planes ---------------------
__global__ void first_kernel(const float* __restrict__ initrec, const float* __restrict__ Wf,
                             const float* __restrict__ aM,
                             __nv_bfloat16* __restrict__ outH, __nv_bfloat16* __restrict__ outL) {
    const int tx = blockIdx.x, ty = blockIdx.y, n = blockIdx.z;
    __shared__ float sI[18][18];
    __shared__ float sWf[576];
    for (int e = threadIdx.x; e < 324; e += 256) {
        int yy = e / 18, xx = e % 18, gy = ty * 16 - 1 + yy, gx = tx * 16 - 1 + xx;
        sI[yy][xx] = ((unsigned)gy < 256u && (unsigned)gx < 256u) ? initrec[n * HWSZ + gy * 256 + gx] : 0.f;
    }
    for (int e = threadIdx.x; e < 576; e += 256) sWf[e] = Wf[e];
    __syncthreads();
    const float a = aM[0];
    const int co = threadIdx.x & 63, pl = threadIdx.x >> 6;
    float wr[9];
#pragma unroll
    for (int k = 0; k < 9; k++) wr[k] = sWf[co * 9 + k];
    for (int pxi = 0; pxi < 64; pxi++) {
        int px = pxi * 4 + pl, r = px >> 4, c = px & 15;
        float s = 0.f;
#pragma unroll
        for (int ky = 0; ky < 3; ky++)
#pragma unroll
            for (int kx = 0; kx < 3; kx++) s += wr[ky * 3 + kx] * sI[r + ky][c + kx];
        s = prelu_f(s, a);
        __nv_bfloat16 h = __float2bfloat16(s);
        __nv_bfloat16 l = __float2bfloat16(s - __bfloat162float(h));
        size_t ad = ((size_t)(n * HWSZ + (ty * 16 + r) * 256 + tx * 16 + c)) * 64 + co;
        outH[ad] = h;
        outL[ad] = l;
    }
}

// ---------- res-block conv 64->64: 2-row tiles, 5-slot ring, B resident ----
// grid (64, 16): x-col = (bx&3)*64, y-group = (bx>>2)*16. 256 thr, 8 warps.
// Slab slot (XOR swizzle, no pad): [plane 2][px 66][128B]; dst chunk:
//   px*128 + (ch*16 ^ ((px&7)<<4))
__device__ __forceinline__ void load_row(uint32_t sb, const __nv_bfloat16* inH,
                                         const __nv_bfloat16* inL, int n, int y,
                                         int x0, int slot, int tid) {
    uint32_t base = sb + SA_OFF + (uint32_t)slot * SLOT_SZ;
    for (int idx = tid; idx < 1056; idx += 256) {
        int plane = idx >= 528;
        int i2 = plane ? idx - 528 : idx;
        int px = i2 >> 3, ch = i2 & 7;
        int gx = x0 - 1 + px;
        bool ok = (unsigned)y < 256u && (unsigned)gx < 256u;
        const __nv_bfloat16* bp = plane ? inL : inH;
        const __nv_bfloat16* sp = ok ? bp + ((size_t)(n * HWSZ + y * 256 + gx)) * 64 + ch * 8 : bp;
        uint32_t dst = base + (uint32_t)plane * 8448 + (uint32_t)px * 128 +
                       (((uint32_t)ch << 4) ^ (((uint32_t)px & 7) << 4));
        cpa16(dst, sp, ok ? 16 : 0);
    }
}

template <bool RES>
__global__ void __launch_bounds__(256, 1) blk_mma(
    const __nv_bfloat16* __restrict__ inH, const __nv_bfloat16* __restrict__ inL,
    const unsigned char* __restrict__ wblk, const float* __restrict__ aB,
    __nv_bfloat16* __restrict__ outH, __nv_bfloat16* __restrict__ outL) {
    extern __shared__ unsigned char sm[];
    const uint32_t sb = smem_u32(sm);
    const int tid = threadIdx.x, w = tid >> 5, lane = tid & 31;
    const int n = blockIdx.y, x0 = (blockIdx.x & 3) * 64, y0 = (blockIdx.x >> 2) * 16;

    // B (all 9 taps) + first 3 rows (rel 0,1,2), one group
    {
        const uint4* s = (const uint4*)wblk;
        for (int i = tid; i < 9216; i += 256) cpa16f(sb + i * 16, s + i);
    }
    load_row(sb, inH, inL, n, y0 - 1, x0, 0, tid);
    load_row(sb, inH, inL, n, y0,     x0, 1, tid);
    load_row(sb, inH, inL, n, y0 + 1, x0, 2, tid);
    CPA_COMMIT();

    // per-lane constants
    const int mf = w & 3, co0 = (w >> 2) * 32;
    const int pxl = mf * 16 + (lane & 15);
    const uint32_t h16 = ((lane >> 4) & 1) << 4;
    const int co_l = (lane & 7) + ((lane >> 4) & 1) * 8;
    const int kb_l = ((lane >> 3) & 1) * 16;
    const int sx = (lane & 7) << 4;
    uint32_t offk[8];
#pragma unroll
    for (int j = 0; j < 8; j++) {
        int kb = j * 32 + kb_l;
        offk[j] = (uint32_t)((kb & 128) | ((kb & 127) ^ sx));
    }
    const uint32_t bbase = sb + (uint32_t)(co0 + co_l) * 256;
    const float a = aB[0];

    for (int t = 0; t < 8; t++) {
        // exposed load: rel 2t+3 (row y0+2t+2); prefetch: rel 2t+4 (row y0+2t+3)
        load_row(sb, inH, inL, n, y0 + 2 * t + 2, x0, (2 * t + 3) % 5, tid);
        CPA_COMMIT();
        if (t < 7)
            load_row(sb, inH, inL, n, y0 + 2 * t + 3, x0, (2 * t + 4) % 5, tid);
        CPA_COMMIT();
        CPA_WAIT1();          // exposed (and older) groups done; prefetch in flight
        __syncthreads();

        // slot base addresses for j = r+ky in 0..3  (rel = 2t+j)
        uint32_t slotA[4];
#pragma unroll
        for (int j = 0; j < 4; j++)
            slotA[j] = sb + SA_OFF + (uint32_t)((2 * t + j) % 5) * SLOT_SZ;

        float acc[2][4][4];
#pragma unroll
        for (int r = 0; r < 2; r++)
#pragma unroll
            for (int i = 0; i < 4; i++)
#pragma unroll
                for (int j = 0; j < 4; j++) acc[r][i][j] = 0.f;

#pragma unroll
        for (int ky = 0; ky < 3; ky++) {
#pragma unroll
            for (int kx = 0; kx < 3; kx++) {
                const uint32_t px = (uint32_t)(pxl + kx);
                const uint32_t sw = (px & 7) << 4;
                uint32_t offs[4];
#pragma unroll
                for (int q = 0; q < 4; q++)
                    offs[q] = ((h16 | ((uint32_t)q << 5)) ^ sw);
                uint32_t ah[2][4][4], al[2][4][4];
#pragma unroll
                for (int r = 0; r < 2; r++) {
                    const uint32_t ab = slotA[r + ky] + px * 128;
#pragma unroll
                    for (int q = 0; q < 4; q++) {
                        ldsm4(ah[r][q], ab + offs[q]);
                        ldsm4(al[r][q], ab + 8448 + offs[q]);
                    }
                }
                const uint32_t bt = bbase + (uint32_t)(ky * 3 + kx) * 16384;
#pragma unroll
                for (int np = 0; np < 2; np++) {
                    const uint32_t bb = bt + np * 4096;
                    uint32_t bf[8][4];
#pragma unroll
                    for (int ks = 0; ks < 8; ks++) ldsm4(bf[ks], bb + offk[ks]);
#pragma unroll
                    for (int ks = 0; ks < 4; ks++) {   // wh: x-hi and x-lo
#pragma unroll
                        for (int r = 0; r < 2; r++) {
                            mma16816(acc[r][np*2+0], ah[r][ks], bf[ks][0], bf[ks][1]);
                            mma16816(acc[r][np*2+1], ah[r][ks], bf[ks][2], bf[ks][3]);
                            mma16816(acc[r][np*2+0], al[r][ks], bf[ks][0], bf[ks][1]);
                            mma16816(acc[r][np*2+1], al[r][ks], bf[ks][2], bf[ks][3]);
                        }
                    }
#pragma unroll
                    for (int ks = 0; ks < 4; ks++) {   // wl: x-hi only
#pragma unroll
                        for (int r = 0; r < 2; r++) {
                            mma16816(acc[r][np*2+0], ah[r][ks], bf[4+ks][0], bf[4+ks][1]);
                            mma16816(acc[r][np*2+1], ah[r][ks], bf[4+ks][2], bf[4+ks][3]);
                        }
                    }
                }
            }
        }

        // epilogue: residual + PReLU + split store (2 rows)
        const int r0 = lane >> 2;
#pragma unroll
        for (int r = 0; r < 2; r++) {
            const size_t rowbase = (size_t)(n * HWSZ + (y0 + 2 * t + r) * 256 + x0 + mf * 16);
#pragma unroll
            for (int h = 0; h < 2; h++) {
                size_t pa = (rowbase + r0 + h * 8) * 64 + co0 + (lane & 3) * 2;
#pragma unroll
                for (int nf = 0; nf < 4; nf++) {
                    size_t ad = pa + nf * 8;
                    float v0 = acc[r][nf][h * 2 + 0], v1 = acc[r][nf][h * 2 + 1];
                    if (RES) {
                        uint32_t h2 = *(const uint32_t*)(outH + ad);
                        uint32_t l2 = *(const uint32_t*)(outL + ad);
                        v0 += __bfloat162float(__ushort_as_bfloat16((unsigned short)(h2 & 0xffff))) +
                              __bfloat162float(__ushort_as_bfloat16((unsigned short)(l2 & 0xffff)));
                        v1 += __bfloat162float(__ushort_as_bfloat16((unsigned short)(h2 >> 16))) +
                              __bfloat162float(__ushort_as_bfloat16((unsigned short)(l2 >> 16)));
                    }
                    v0 = prelu_f(v0, a);
                    v1 = prelu_f(v1, a);
                    __nv_bfloat16 h0 = __float2bfloat16(v0), h1 = __float2bfloat16(v1);
                    __nv_bfloat16 l0 = __float2bfloat16(v0 - __bfloat162float(h0));
                    __nv_bfloat16 l1 = __float2bfloat16(v1 - __bfloat162float(h1));
                    *(uint32_t*)(outH + ad) = (uint32_t)__bfloat16_as_ushort(h0) |
                                              ((uint32_t)__bfloat16_as_ushort(h1) << 16);
                    *(uint32_t*)(outL + ad) = (uint32_t)__bfloat16_as_ushort(l0) |
                                              ((uint32_t)__bfloat16_as_ushort(l1) << 16);
                }
            }
        }
        __syncthreads();   // slab reads done before next tile's loads land
    }
}

// --------- last conv: (feat planes + initrec) -> 1 channel -----------------
__global__ void last_kernel(const __nv_bfloat16* __restrict__ featH,
                            const __nv_bfloat16* __restrict__ featL,
                            const float* __restrict__ initrec,
                            const float* __restrict__ Wl, float* __restrict__ out) {
    const int tx = blockIdx.x, ty = blockIdx.y, n = blockIdx.z;
    __shared__ float sInit[18][18];
    __shared__ float sIn[8][18][20];
    __shared__ float sWl[576];
    for (int e = threadIdx.x; e < 324; e += 256) {
        int yy = e / 18, xx = e % 18, gy = ty * 16 - 1 + yy, gx = tx * 16 - 1 + xx;
        sInit[yy][xx] = ((unsigned)gy < 256u && (unsigned)gx < 256u) ? initrec[n * HWSZ + gy * 256 + gx] : 0.f;
    }
    for (int e = threadIdx.x; e < 576; e += 256) sWl[e] = Wl[e];
    __syncthreads();
    const int r = threadIdx.x >> 4, c = threadIdx.x & 15;
    float acc = 0.f;
    for (int ci0 = 0; ci0 < 64; ci0 += 8) {
        for (int e = threadIdx.x; e < 2592; e += 256) {
            int px = e >> 3, ci = e & 7, yy = px / 18, xx = px % 18;
            int gy = ty * 16 - 1 + yy, gx = tx * 16 - 1 + xx;
            float v = 0.f;
            if ((unsigned)gy < 256u && (unsigned)gx < 256u) {
                size_t ad = (size_t)(n * HWSZ + gy * 256 + gx) * 64 + ci0 + ci;
                v = __bfloat162float(featH[ad]) + __bfloat162float(featL[ad]);
            }
            sIn[ci][yy][xx] = v + sInit[yy][xx];
        }
        __syncthreads();
#pragma unroll 1
        for (int ci = 0; ci < 8; ci++)
#pragma unroll
            for (int ky = 0; ky < 3; ky++)
#pragma unroll
                for (int kx = 0; kx < 3; kx++)
                    acc += sIn[ci][r + ky][c + kx] * sWl[(ci0 + ci) * 9 + ky * 3 + kx];
        __syncthreads();
    }
    out[n * HWSZ + (ty * 16 + r) * 256 + (tx * 16 + c)] = acc;
}

// ---------------------------------------------------------------------------
extern "C" void kernel_launch(void* const* d_in, const int* in_sizes, int n_in,
                              void* d_out, int out_size) {
    (void)in_sizes; (void)n_in; (void)out_size;
    const float* x   = (const float*)d_in[0];
    const float* Wcs = (const float*)d_in[1];
    const float* Wi  = (const float*)d_in[2];
    const float* Wf  = (const float*)d_in[3];
    const float* Wb  = (const float*)d_in[4];
    const float* Wl  = (const float*)d_in[5];
    const float* aM  = (const float*)d_in[6];
    const float* aB  = (const float*)d_in[7];

    float* out     = (float*)d_out;
    float* csy     = out + 16 * HWSZ;
    float* initrec = csy + 16 * 256 * 64;

    void *pA = nullptr, *pB = nullptr, *pW = nullptr;
    cudaGetSymbolAddress(&pA, g_featA);
    cudaGetSymbolAddress(&pB, g_featB);
    cudaGetSymbolAddress(&pW, g_wblk);
    __nv_bfloat16* hiA = (__nv_bfloat16*)pA;
    __nv_bfloat16* loA = hiA + PLANE;
    __nv_bfloat16* hiB = (__nv_bfloat16*)pB;
    __nv_bfloat16* loB = hiB + PLANE;
    unsigned char* wblk = (unsigned char*)pW;

    cudaFuncSetAttribute(blk_mma<false>, cudaFuncAttributeMaxDynamicSharedMemorySize, SMEM_BLK);
    cudaFuncSetAttribute(blk_mma<true>,  cudaFuncAttributeMaxDynamicSharedMemorySize, SMEM_BLK);

    wprep_kernel<<<(9 * 64 * 128 + 255) / 256, 256>>>(Wb, wblk);
    cs_kernel<<<dim3(8, 16), 256>>>(x, Wcs, csy);
    init_kernel<<<dim3(8, 16), 256>>>(csy, Wi, initrec);
    first_kernel<<<dim3(16, 16, 16), 256>>>(initrec, Wf, aM, hiA, loA);

    for (int i = 0; i < 4; i++) {
        blk_mma<false><<<dim3(64, 16), 256, SMEM_BLK>>>(hiA, loA, wblk, aB, hiB, loB);
        blk_mma<true><<<dim3(64, 16), 256, SMEM_BLK>>>(hiB, loB, wblk, aB, hiA, loA);
    }
    last_kernel<<<dim3(16, 16, 16), 256>>>(hiA, loA, initrec, Wl, out);
}

// round 10
// speedup vs baseline: 1.3194x; 1.2599x over previous
#include <cuda_runtime.h>
#include <cuda_bf16.h>
#include <cstdint>

#define HWSZ 65536
#define FEAT (16*64*HWSZ)
#define PLANE ((size_t)16*HWSZ*64)

__device__ float g_featA[FEAT];
__device__ float g_featB[FEAT];
__device__ unsigned char g_wblk[147456];   // [tap 9][co 64][K 128] bf16, swizzled

#define SA_OFF 147456
#define SLOT_SZ 16896                      // 2 planes x 66px x 128B, XOR-swizzled
#define SMEM_BLK (147456 + 4 * SLOT_SZ)    // 215,040 B

__device__ __forceinline__ float prelu_f(float v, float a) { return v >= 0.f ? v : a * v; }

__device__ __forceinline__ uint32_t smem_u32(const void* p) {
    uint32_t a;
    asm("{ .reg .u64 t; cvta.to.shared.u64 t, %1; cvt.u32.u64 %0, t; }" : "=r"(a) : "l"(p));
    return a;
}
__device__ __forceinline__ void ldsm4(uint32_t* r, uint32_t addr) {
    asm volatile("ldmatrix.sync.aligned.m8n8.x4.shared.b16 {%0,%1,%2,%3}, [%4];"
                 : "=r"(r[0]), "=r"(r[1]), "=r"(r[2]), "=r"(r[3]) : "r"(addr));
}
__device__ __forceinline__ void mma16816(float* d, const uint32_t* a, uint32_t b0, uint32_t b1) {
    asm volatile("mma.sync.aligned.m16n8k16.row.col.f32.bf16.bf16.f32 "
                 "{%0,%1,%2,%3},{%4,%5,%6,%7},{%8,%9},{%0,%1,%2,%3};"
                 : "+f"(d[0]), "+f"(d[1]), "+f"(d[2]), "+f"(d[3])
                 : "r"(a[0]), "r"(a[1]), "r"(a[2]), "r"(a[3]), "r"(b0), "r"(b1));
}
__device__ __forceinline__ void cpa16(uint32_t dst, const void* src, int sz) {
    asm volatile("cp.async.cg.shared.global [%0], [%1], 16, %2;" :: "r"(dst), "l"(src), "r"(sz));
}
__device__ __forceinline__ void cpa16f(uint32_t dst, const void* src) {
    asm volatile("cp.async.cg.shared.global [%0], [%1], 16;" :: "r"(dst), "l"(src));
}
#define CPA_COMMIT() asm volatile("cp.async.commit_group;")
#define CPA_WAIT1()  asm volatile("cp.async.wait_group 1;")
#define CPA_WAIT0()  asm volatile("cp.async.wait_group 0;")

// ---- weight prep: Wb fp32 -> swizzled [tap][co][K=128: wh(64)|wl(64)] ----
__global__ void wprep_kernel(const float* __restrict__ Wb, unsigned char* __restrict__ wsp) {
    int i = blockIdx.x * 256 + threadIdx.x;
    if (i >= 9 * 64 * 128) return;
    int k = i & 127, co = (i >> 7) & 63, tap = i >> 13;
    int ci = k & 63, seg = k >> 6;
    float w = Wb[co * 576 + ci * 9 + tap];
    __nv_bfloat16 h = __float2bfloat16(w);
    __nv_bfloat16 v = seg ? __float2bfloat16(w - __bfloat162float(h)) : h;
    int kb = 2 * k;
    int off = (kb & 128) | ((kb & 127) ^ ((co & 7) << 4));
    *(__nv_bfloat16*)(wsp + tap * 16384 + co * 256 + off) = v;
}

// ---------------- CS sampling conv (fp32) ----------------------------------
__global__ void cs_kernel(const float* __restrict__ x, const float* __restrict__ Wcs,
                          float* __restrict__ csy) {
    const int pg = blockIdx.x, n = blockIdx.y, f = threadIdx.x;
    __shared__ float sX[8][32];
    __shared__ float sW[256][33];
    float acc[8] = {};
    for (int k0 = 0; k0 < 1024; k0 += 32) {
        const int i = k0 >> 5;
        int p = threadIdx.x >> 5, kk = threadIdx.x & 31;
        sX[p][kk] = x[n * HWSZ + (pg * 32 + i) * 256 + p * 32 + kk];
        for (int e = threadIdx.x; e < 8192; e += 256)
            sW[e >> 5][e & 31] = Wcs[(e >> 5) * 1024 + k0 + (e & 31)];
        __syncthreads();
#pragma unroll
        for (int q = 0; q < 32; q++) {
            float w = sW[f][q];
#pragma unroll
            for (int pp = 0; pp < 8; pp++) acc[pp] += sX[pp][q] * w;
        }
        __syncthreads();
    }
#pragma unroll
    for (int pp = 0; pp < 8; pp++) csy[(n * 256 + f) * 64 + pg * 8 + pp] = acc[pp];
}

// ---------------- init reconstruction (fp32) -------------------------------
__global__ void init_kernel(const float* __restrict__ csy, const float* __restrict__ Wi,
                            float* __restrict__ initrec) {
    const int cb = blockIdx.x * 128, n = blockIdx.y;
    const int cg = threadIdx.x >> 3, pgl = threadIdx.x & 7;
    __shared__ float sX[32][64];
    __shared__ float sW[128][33];
    float acc[4][8] = {};
    for (int k0 = 0; k0 < 256; k0 += 32) {
        for (int e = threadIdx.x; e < 2048; e += 256)
            sX[e >> 6][e & 63] = csy[(n * 256 + k0 + (e >> 6)) * 64 + (e & 63)];
        for (int e = threadIdx.x; e < 4096; e += 256)
            sW[e >> 5][e & 31] = Wi[(cb + (e >> 5)) * 256 + k0 + (e & 31)];
        __syncthreads();
#pragma unroll
        for (int kk = 0; kk < 32; kk++) {
            float w0 = sW[cg*4+0][kk], w1 = sW[cg*4+1][kk], w2 = sW[cg*4+2][kk], w3 = sW[cg*4+3][kk];
#pragma unroll
            for (int pp = 0; pp < 8; pp++) {
                float xv = sX[kk][pgl * 8 + pp];
                acc[0][pp] += w0*xv; acc[1][pp] += w1*xv; acc[2][pp] += w2*xv; acc[3][pp] += w3*xv;
            }
        }
        __syncthreads();
    }
#pragma unroll
    for (int jc = 0; jc < 4; jc++) {
        int c = cb + cg * 4 + jc, jj = c >> 5, ii = c & 31;
#pragma unroll
        for (int pp = 0; pp < 8; pp++) {
            int pos = pgl * 8 + pp, by = pos >> 3, bx = pos & 7;
            initrec[n * HWSZ + (by * 32 + ii) * 256 + (bx * 32 + jj)] = acc[jc][pp];
        }
    }
}

// ------- first conv 1->64 + PReLU -> hi/lo bf16 planes ---------------------
__global__ void first_kernel(const float* __restrict__ initrec, const float* __restrict__ Wf,
                             const float* __restrict__ aM,
                             __nv_bfloat16* __restrict__ outH, __nv_bfloat16* __restrict__ outL) {
    const int tx = blockIdx.x, ty = blockIdx.y, n = blockIdx.z;
    __shared__ float sI[18][18];
    __shared__ float sWf[576];
    for (int e = threadIdx.x; e < 324; e += 256) {
        int yy = e / 18, xx = e % 18, gy = ty * 16 - 1 + yy, gx = tx * 16 - 1 + xx;
        sI[yy][xx] = ((unsigned)gy < 256u && (unsigned)gx < 256u) ? initrec[n * HWSZ + gy * 256 + gx] : 0.f;
    }
    for (int e = threadIdx.x; e < 576; e += 256) sWf[e] = Wf[e];
    __syncthreads();
    const float a = aM[0];
    const int co = threadIdx.x & 63, pl = threadIdx.x >> 6;
    float wr[9];
#pragma unroll
    for (int k = 0; k < 9; k++) wr[k] = sWf[co * 9 + k];
    for (int pxi = 0; pxi < 64; pxi++) {
        int px = pxi * 4 + pl, r = px >> 4, c = px & 15;
        float s = 0.f;
#pragma unroll
        for (int ky = 0; ky < 3; ky++)
#pragma unroll
            for (int kx = 0; kx < 3; kx++) s += wr[ky * 3 + kx] * sI[r + ky][c + kx];
        s = prelu_f(s, a);
        __nv_bfloat16 h = __float2bfloat16(s);
        __nv_bfloat16 l = __float2bfloat16(s - __bfloat162float(h));
        size_t ad = ((size_t)(n * HWSZ + (ty * 16 + r) * 256 + tx * 16 + c)) * 64 + co;
        outH[ad] = h;
        outL[ad] = l;
    }
}

// ---------- res-block conv 64->64: 2-row tiles, 16 warps (4/SMSP) ----------
// grid (64, 16): x-col = (bx&3)*64, y-group = (bx>>2)*16. 512 thr, 16 warps:
// warp = m(4, 16px) x ng(4, 16co). 4-slot row ring, XOR swizzle.
__device__ __forceinline__ void load_row(uint32_t sb, const __nv_bfloat16* inH,
                                         const __nv_bfloat16* inL, int n, int y,
                                         int x0, int slot, int tid) {
    uint32_t base = sb + SA_OFF + (uint32_t)slot * SLOT_SZ;
    for (int idx = tid; idx < 1056; idx += 512) {
        int plane = idx >= 528;
        int i2 = plane ? idx - 528 : idx;
        int px = i2 >> 3, ch = i2 & 7;
        int gx = x0 - 1 + px;
        bool ok = (unsigned)y < 256u && (unsigned)gx < 256u;
        const __nv_bfloat16* bp = plane ? inL : inH;
        const __nv_bfloat16* sp = ok ? bp + ((size_t)(n * HWSZ + y * 256 + gx)) * 64 + ch * 8 : bp;
        uint32_t dst = base + (uint32_t)plane * 8448 + (uint32_t)px * 128 +
                       (((uint32_t)ch << 4) ^ (((uint32_t)px & 7) << 4));
        cpa16(dst, sp, ok ? 16 : 0);
    }
}

template <bool RES>
__global__ void __launch_bounds__(512, 1) blk_mma(
    const __nv_bfloat16* __restrict__ inH, const __nv_bfloat16* __restrict__ inL,
    const unsigned char* __restrict__ wblk, const float* __restrict__ aB,
    __nv_bfloat16* __restrict__ outH, __nv_bfloat16* __restrict__ outL) {
    extern __shared__ unsigned char sm[];
    const uint32_t sb = smem_u32(sm);
    const int tid = threadIdx.x, w = tid >> 5, lane = tid & 31;
    const int n = blockIdx.y, x0 = (blockIdx.x & 3) * 64, y0 = (blockIdx.x >> 2) * 16;
    const int m = w & 3, ng = w >> 2;

    // Prologue: B (all taps) + rows rel 0,1,2 in group A; rel 3 in group B.
    {
        const uint4* s = (const uint4*)wblk;
        for (int i = tid; i < 9216; i += 512) cpa16f(sb + i * 16, s + i);
    }
    load_row(sb, inH, inL, n, y0 - 1, x0, 0, tid);   // rel 0
    load_row(sb, inH, inL, n, y0,     x0, 1, tid);   // rel 1
    load_row(sb, inH, inL, n, y0 + 1, x0, 2, tid);   // rel 2
    CPA_COMMIT();
    load_row(sb, inH, inL, n, y0 + 2, x0, 3, tid);   // rel 3
    CPA_COMMIT();

    // per-lane constants
    const int pxl = m * 16 + (lane & 15);
    const uint32_t h16 = ((lane >> 4) & 1) << 4;
    const int co_l = (lane & 7) + ((lane >> 4) & 1) * 8;
    const int kb_l = ((lane >> 3) & 1) * 16;
    const int sx = (lane & 7) << 4;
    uint32_t offk[8];
#pragma unroll
    for (int j = 0; j < 8; j++) {
        int kb = j * 32 + kb_l;
        offk[j] = (uint32_t)((kb & 128) | ((kb & 127) ^ sx));
    }
    const uint32_t bbase = sb + (uint32_t)(ng * 16 + co_l) * 256;
    const float a = aB[0];

    for (int t = 0; t < 8; t++) {
        // slot bases for j = r+ky (rel = 2t+j)
        uint32_t slotA[4];
#pragma unroll
        for (int j = 0; j < 4; j++)
            slotA[j] = sb + SA_OFF + (uint32_t)((2 * t + j) & 3) * SLOT_SZ;

        float acc[2][2][4];
#pragma unroll
        for (int r = 0; r < 2; r++)
#pragma unroll
            for (int i = 0; i < 2; i++)
#pragma unroll
                for (int j = 0; j < 4; j++) acc[r][i][j] = 0.f;

        CPA_WAIT1();          // rels <= 2t+2 resident; rel 2t+3 in flight
        __syncthreads();

#pragma unroll
        for (int ky = 0; ky < 3; ky++) {
            if (ky == 2) {    // rel 2t+3 first needed at j=3 (r=1, ky=2)
                CPA_WAIT0();
                __syncthreads();
            }
#pragma unroll
            for (int kx = 0; kx < 3; kx++) {
                const uint32_t px = (uint32_t)(pxl + kx);
                const uint32_t sw = (px & 7) << 4;
                const uint32_t a0 = slotA[ky + 0] + px * 128;   // row r=0
                const uint32_t a1 = slotA[ky + 1] + px * 128;   // row r=1
                const uint32_t bt = bbase + (uint32_t)(ky * 3 + kx) * 16384;
#pragma unroll
                for (int q = 0; q < 4; q++) {
                    const uint32_t off = (h16 | ((uint32_t)q << 5)) ^ sw;
                    uint32_t ah0[4], ah1[4], al0[4], al1[4], bh[4], bl[4];
                    ldsm4(ah0, a0 + off);
                    ldsm4(ah1, a1 + off);
                    ldsm4(al0, a0 + 8448 + off);
                    ldsm4(al1, a1 + 8448 + off);
                    ldsm4(bh, bt + offk[q]);
                    ldsm4(bl, bt + offk[4 + q]);
                    // wh x (xh, xl); wl x xh
                    mma16816(acc[0][0], ah0, bh[0], bh[1]);
                    mma16816(acc[0][1], ah0, bh[2], bh[3]);
                    mma16816(acc[1][0], ah1, bh[0], bh[1]);
                    mma16816(acc[1][1], ah1, bh[2], bh[3]);
                    mma16816(acc[0][0], al0, bh[0], bh[1]);
                    mma16816(acc[0][1], al0, bh[2], bh[3]);
                    mma16816(acc[1][0], al1, bh[0], bh[1]);
                    mma16816(acc[1][1], al1, bh[2], bh[3]);
                    mma16816(acc[0][0], ah0, bl[0], bl[1]);
                    mma16816(acc[0][1], ah0, bl[2], bl[3]);
                    mma16816(acc[1][0], ah1, bl[0], bl[1]);
                    mma16816(acc[1][1], ah1, bl[2], bl[3]);
                }
            }
        }
        __syncthreads();      // slab reads done

        // issue next tile's rows (rels 2t+4, 2t+5) — overlap with epilogue
        if (t < 7) {
            load_row(sb, inH, inL, n, y0 + 2 * t + 3, x0, (2 * t + 4) & 3, tid);
            CPA_COMMIT();
            load_row(sb, inH, inL, n, y0 + 2 * t + 4, x0, (2 * t + 5) & 3, tid);
            CPA_COMMIT();
        }

        // epilogue: residual + PReLU + split store (2 rows x 16px x 16co)
        const int r0 = lane >> 2;
#pragma unroll
        for (int r = 0; r < 2; r++) {
            const size_t rowbase = (size_t)(n * HWSZ + (y0 + 2 * t + r) * 256 + x0 + m * 16);
#pragma unroll
            for (int h = 0; h < 2; h++) {
                size_t pa = (rowbase + r0 + h * 8) * 64 + ng * 16 + (lane & 3) * 2;
#pragma unroll
                for (int q = 0; q < 2; q++) {
                    size_t ad = pa + q * 8;
                    float v0 = acc[r][q][h * 2 + 0], v1 = acc[r][q][h * 2 + 1];
                    if (RES) {
                        uint32_t h2 = *(const uint32_t*)(outH + ad);
                        uint32_t l2 = *(const uint32_t*)(outL + ad);
                        v0 += __bfloat162float(__ushort_as_bfloat16((unsigned short)(h2 & 0xffff))) +
                              __bfloat162float(__ushort_as_bfloat16((unsigned short)(l2 & 0xffff)));
                        v1 += __bfloat162float(__ushort_as_bfloat16((unsigned short)(h2 >> 16))) +
                              __bfloat162float(__ushort_as_bfloat16((unsigned short)(l2 >> 16)));
                    }
                    v0 = prelu_f(v0, a);
                    v1 = prelu_f(v1, a);
                    __nv_bfloat16 h0 = __float2bfloat16(v0), h1 = __float2bfloat16(v1);
                    __nv_bfloat16 l0 = __float2bfloat16(v0 - __bfloat162float(h0));
                    __nv_bfloat16 l1 = __float2bfloat16(v1 - __bfloat162float(h1));
                    *(uint32_t*)(outH + ad) = (uint32_t)__bfloat16_as_ushort(h0) |
                                              ((uint32_t)__bfloat16_as_ushort(h1) << 16);
                    *(uint32_t*)(outL + ad) = (uint32_t)__bfloat16_as_ushort(l0) |
                                              ((uint32_t)__bfloat16_as_ushort(l1) << 16);
                }
            }
        }
        __syncthreads();      // epilogue/residual reads done before slots reused
    }
}

// --------- last conv: (feat planes + initrec) -> 1 channel -----------------
__global__ void last_kernel(const __nv_bfloat16* __restrict__ featH,
                            const __nv_bfloat16* __restrict__ featL,
                            const float* __restrict__ initrec,
                            const float* __restrict__ Wl, float* __restrict__ out) {
    const int tx = blockIdx.x, ty = blockIdx.y, n = blockIdx.z;
    __shared__ float sInit[18][18];
    __shared__ float sIn[8][18][20];
    __shared__ float sWl[576];
    for (int e = threadIdx.x; e < 324; e += 256) {
        int yy = e / 18, xx = e % 18, gy = ty * 16 - 1 + yy, gx = tx * 16 - 1 + xx;
        sInit[yy][xx] = ((unsigned)gy < 256u && (unsigned)gx < 256u) ? initrec[n * HWSZ + gy * 256 + gx] : 0.f;
    }
    for (int e = threadIdx.x; e < 576; e += 256) sWl[e] = Wl[e];
    __syncthreads();
    const int r = threadIdx.x >> 4, c = threadIdx.x & 15;
    float acc = 0.f;
    for (int ci0 = 0; ci0 < 64; ci0 += 8) {
        for (int e = threadIdx.x; e < 2592; e += 256) {
            int px = e >> 3, ci = e & 7, yy = px / 18, xx = px % 18;
            int gy = ty * 16 - 1 + yy, gx = tx * 16 - 1 + xx;
            float v = 0.f;
            if ((unsigned)gy < 256u && (unsigned)gx < 256u) {
                size_t ad = (size_t)(n * HWSZ + gy * 256 + gx) * 64 + ci0 + ci;
                v = __bfloat162float(featH[ad]) + __bfloat162float(featL[ad]);
            }
            sIn[ci][yy][xx] = v + sInit[yy][xx];
        }
        __syncthreads();
#pragma unroll 1
        for (int ci = 0; ci < 8; ci++)
#pragma unroll
            for (int ky = 0; ky < 3; ky++)
#pragma unroll
                for (int kx = 0; kx < 3; kx++)
                    acc += sIn[ci][r + ky][c + kx] * sWl[(ci0 + ci) * 9 + ky * 3 + kx];
        __syncthreads();
    }
    out[n * HWSZ + (ty * 16 + r) * 256 + (tx * 16 + c)] = acc;
}

// ---------------------------------------------------------------------------
extern "C" void kernel_launch(void* const* d_in, const int* in_sizes, int n_in,
                              void* d_out, int out_size) {
    (void)in_sizes; (void)n_in; (void)out_size;
    const float* x   = (const float*)d_in[0];
    const float* Wcs = (const float*)d_in[1];
    const float* Wi  = (const float*)d_in[2];
    const float* Wf  = (const float*)d_in[3];
    const float* Wb  = (const float*)d_in[4];
    const float* Wl  = (const float*)d_in[5];
    const float* aM  = (const float*)d_in[6];
    const float* aB  = (const float*)d_in[7];

    float* out     = (float*)d_out;
    float* csy     = out + 16 * HWSZ;
    float* initrec = csy + 16 * 256 * 64;

    void *pA = nullptr, *pB = nullptr, *pW = nullptr;
    cudaGetSymbolAddress(&pA, g_featA);
    cudaGetSymbolAddress(&pB, g_featB);
    cudaGetSymbolAddress(&pW, g_wblk);
    __nv_bfloat16* hiA = (__nv_bfloat16*)pA;
    __nv_bfloat16* loA = hiA + PLANE;
    __nv_bfloat16* hiB = (__nv_bfloat16*)pB;
    __nv_bfloat16* loB = hiB + PLANE;
    unsigned char* wblk = (unsigned char*)pW;

    cudaFuncSetAttribute(blk_mma<false>, cudaFuncAttributeMaxDynamicSharedMemorySize, SMEM_BLK);
    cudaFuncSetAttribute(blk_mma<true>,  cudaFuncAttributeMaxDynamicSharedMemorySize, SMEM_BLK);

    wprep_kernel<<<(9 * 64 * 128 + 255) / 256, 256>>>(Wb, wblk);
    cs_kernel<<<dim3(8, 16), 256>>>(x, Wcs, csy);
    init_kernel<<<dim3(8, 16), 256>>>(csy, Wi, initrec);
    first_kernel<<<dim3(16, 16, 16), 256>>>(initrec, Wf, aM, hiA, loA);

    for (int i = 0; i < 4; i++) {
        blk_mma<false><<<dim3(64, 16), 512, SMEM_BLK>>>(hiA, loA, wblk, aB, hiB, loB);
        blk_mma<true><<<dim3(64, 16), 512, SMEM_BLK>>>(hiB, loB, wblk, aB, hiA, loA);
    }
    last_kernel<<<dim3(16, 16, 16), 256>>>(hiA, loA, initrec, Wl, out);
}